// round 2
// baseline (speedup 1.0000x reference)
#include <cuda_runtime.h>
#include <stdint.h>

#define MAX_NODES 50000
#define FIN 512
#define FH  256
#define FO  64

// ---- scratch (no allocations allowed) ----
__device__ int   g_deg[MAX_NODES];
__device__ float g_dinv[MAX_NODES];
__device__ float g_h1[(size_t)MAX_NODES * FH];   // x @ W1
__device__ float g_a1[(size_t)MAX_NODES * FH];   // aggregated layer-1 (bias added)
__device__ float g_h2[(size_t)MAX_NODES * FO];   // relu(a1) @ W2

// ---------------- degree / dinv ----------------
__global__ void k_zero_deg(int n) {
    int i = blockIdx.x * blockDim.x + threadIdx.x;
    if (i < n) g_deg[i] = 0;
}

__global__ void k_count(const int* __restrict__ col, int E) {
    int i = blockIdx.x * blockDim.x + threadIdx.x;
    if (i < E) atomicAdd(&g_deg[col[i]], 1);
}

__global__ void k_dinv(int n) {
    int i = blockIdx.x * blockDim.x + threadIdx.x;
    if (i < n) g_dinv[i] = rsqrtf((float)(g_deg[i] + 1));  // +1 self-loop
}

// ---------------- tiled fp32 GEMM: C[M,N] = op(A[M,K]) @ B[K,N] ----------------
// BM=128, BN=64, BK=16, 256 threads, each thread computes 8x4.
template<int N, int K, bool RELU>
__global__ void __launch_bounds__(256) k_gemm(const float* __restrict__ A,
                                              const float* __restrict__ B,
                                              float* __restrict__ C, int M) {
    constexpr int BM = 128, BN = 64, BK = 16;
    __shared__ float As[BK][BM + 1];
    __shared__ float Bs[BK][BN];

    const int tid = threadIdx.x;
    const int bm = blockIdx.x * BM;
    const int bn = blockIdx.y * BN;
    const int tx = tid & 15;
    const int ty = tid >> 4;
    const int tm0 = ty * 8;
    const int tn0 = tx * 4;

    const int ar = tid >> 2;        // 0..63
    const int ac = (tid & 3) * 4;   // 0,4,8,12
    const int br = tid >> 4;        // 0..15
    const int bc = (tid & 15) * 4;  // 0..60

    float acc[8][4];
#pragma unroll
    for (int i = 0; i < 8; i++)
#pragma unroll
        for (int j = 0; j < 4; j++) acc[i][j] = 0.f;

    for (int k0 = 0; k0 < K; k0 += BK) {
#pragma unroll
        for (int h = 0; h < 2; h++) {
            const int r = ar + h * 64;
            const int grow = bm + r;
            float4 v = make_float4(0.f, 0.f, 0.f, 0.f);
            if (grow < M) {
                v = *reinterpret_cast<const float4*>(A + (size_t)grow * K + k0 + ac);
                if (RELU) {
                    v.x = fmaxf(v.x, 0.f); v.y = fmaxf(v.y, 0.f);
                    v.z = fmaxf(v.z, 0.f); v.w = fmaxf(v.w, 0.f);
                }
            }
            As[ac + 0][r] = v.x; As[ac + 1][r] = v.y;
            As[ac + 2][r] = v.z; As[ac + 3][r] = v.w;
        }
        {
            const float4 bv = *reinterpret_cast<const float4*>(B + (size_t)(k0 + br) * N + bn + bc);
            *reinterpret_cast<float4*>(&Bs[br][bc]) = bv;
        }
        __syncthreads();

#pragma unroll
        for (int k = 0; k < BK; k++) {
            float ra[8], rb[4];
#pragma unroll
            for (int i = 0; i < 8; i++) ra[i] = As[k][tm0 + i];
#pragma unroll
            for (int j = 0; j < 4; j++) rb[j] = Bs[k][tn0 + j];
#pragma unroll
            for (int i = 0; i < 8; i++)
#pragma unroll
                for (int j = 0; j < 4; j++) acc[i][j] = fmaf(ra[i], rb[j], acc[i][j]);
        }
        __syncthreads();
    }

#pragma unroll
    for (int i = 0; i < 8; i++) {
        const int grow = bm + tm0 + i;
        if (grow < M) {
            float4 v = make_float4(acc[i][0], acc[i][1], acc[i][2], acc[i][3]);
            *reinterpret_cast<float4*>(C + (size_t)grow * N + bn + tn0) = v;
        }
    }
}

// ---------------- init: out[i,f] = bias[f] + h[i,f] * dinv[i]^2 (self-loop) ----------------
template<int LOGF4>  // F = 4 << LOGF4
__global__ void k_init(const float* __restrict__ h, const float* __restrict__ bias,
                       float* __restrict__ out, int n) {
    constexpr int F4 = 1 << LOGF4;
    const long long total = (long long)n << LOGF4;
    for (long long idx = blockIdx.x * (long long)blockDim.x + threadIdx.x; idx < total;
         idx += (long long)gridDim.x * blockDim.x) {
        const int i = (int)(idx >> LOGF4);
        const int q = (int)(idx & (F4 - 1));
        float s = g_dinv[i]; s = s * s;
        const size_t off = ((size_t)i << (LOGF4 + 2)) + q * 4;
        const float4 hv = *reinterpret_cast<const float4*>(h + off);
        const float4 bv = *reinterpret_cast<const float4*>(bias + q * 4);
        float4 o;
        o.x = fmaf(hv.x, s, bv.x); o.y = fmaf(hv.y, s, bv.y);
        o.z = fmaf(hv.z, s, bv.z); o.w = fmaf(hv.w, s, bv.w);
        *reinterpret_cast<float4*>(out + off) = o;
    }
}

// ---------------- edge scatter: out[col] += h[row] * dinv[row]*dinv[col] ----------------
template<int LOGF4>
__global__ void k_scatter(const float* __restrict__ h, float* __restrict__ out,
                          const int* __restrict__ row,
                          const int* __restrict__ col, int E) {
    constexpr int F4 = 1 << LOGF4;
    const long long total = (long long)E << LOGF4;
    for (long long idx = blockIdx.x * (long long)blockDim.x + threadIdx.x; idx < total;
         idx += (long long)gridDim.x * blockDim.x) {
        const int e = (int)(idx >> LOGF4);
        const int q = (int)(idx & (F4 - 1));
        const int r = row[e];
        const int c = col[e];
        const float nrm = g_dinv[r] * g_dinv[c];
        const float4 v = *reinterpret_cast<const float4*>(h + ((size_t)r << (LOGF4 + 2)) + q * 4);
        float* o = out + ((size_t)c << (LOGF4 + 2)) + q * 4;
        atomicAdd(o + 0, v.x * nrm);
        atomicAdd(o + 1, v.y * nrm);
        atomicAdd(o + 2, v.z * nrm);
        atomicAdd(o + 3, v.w * nrm);
    }
}

extern "C" void kernel_launch(void* const* d_in, const int* in_sizes, int n_in,
                              void* d_out, int out_size) {
    const float* x   = (const float*)d_in[0];
    const int*   ei  = (const int*)d_in[1];     // int32: JAX x64 disabled
    const float* W1  = (const float*)d_in[2];
    const float* b1  = (const float*)d_in[3];
    const float* W2  = (const float*)d_in[4];
    const float* b2  = (const float*)d_in[5];
    float*       out = (float*)d_out;

    const int M = in_sizes[0] / FIN;        // 50000 nodes
    const int E = in_sizes[1] / 2;          // 800000 edges
    const int* row = ei;
    const int* col = ei + E;

    const int T = 256;

    // degree + dinv
    k_zero_deg<<<(M + T - 1) / T, T>>>(M);
    k_count<<<(E + T - 1) / T, T>>>(col, E);
    k_dinv<<<(M + T - 1) / T, T>>>(M);

    // layer 1: h1 = x @ W1
    {
        dim3 grid((M + 127) / 128, FH / 64);
        k_gemm<FH, FIN, false><<<grid, T>>>(x, W1, g_h1, M);
    }
    // a1 = b1 + h1*dinv^2 (self-loop), then scatter edges
    k_init<6><<<2368, T>>>(g_h1, b1, g_a1, M);
    k_scatter<6><<<2368, T>>>(g_h1, g_a1, row, col, E);

    // layer 2: h2 = relu(a1) @ W2
    {
        dim3 grid((M + 127) / 128, FO / 64);
        k_gemm<FO, FH, true><<<grid, T>>>(g_a1, W2, g_h2, M);
    }
    // out = b2 + h2*dinv^2, then scatter edges
    k_init<4><<<2368, T>>>(g_h2, b2, out, M);
    k_scatter<4><<<2368, T>>>(g_h2, out, row, col, E);
}

// round 3
// speedup vs baseline: 5.2284x; 5.2284x over previous
#include <cuda_runtime.h>
#include <stdint.h>

#define MAX_NODES 50000
#define MAX_EDGES 1000000
#define FIN 512
#define FH  256
#define FO  64

// ---- scratch (no allocations allowed) ----
__device__ int   g_deg[MAX_NODES];
__device__ int   g_off[MAX_NODES + 1];
__device__ int   g_cur[MAX_NODES];
__device__ int   g_adj[MAX_EDGES];               // source node per CSR slot
__device__ float g_dinv[MAX_NODES];
__device__ float g_h1[(size_t)MAX_NODES * FH];   // (x @ W1) * dinv[row]
__device__ float g_a1[(size_t)MAX_NODES * FH];   // relu(aggregated layer-1)
__device__ float g_h2[(size_t)MAX_NODES * FO];   // (a1 @ W2) * dinv[row]

// ---------------- degree / dinv ----------------
__global__ void k_zero_deg(int n) {
    int i = blockIdx.x * blockDim.x + threadIdx.x;
    if (i < n) g_deg[i] = 0;
}

__global__ void k_count(const int* __restrict__ col, int E) {
    int i = blockIdx.x * blockDim.x + threadIdx.x;
    if (i < E) atomicAdd(&g_deg[col[i]], 1);
}

__global__ void k_dinv(int n) {
    int i = blockIdx.x * blockDim.x + threadIdx.x;
    if (i < n) g_dinv[i] = rsqrtf((float)(g_deg[i] + 1));  // +1 self-loop
}

// ---------------- single-block exclusive scan over degrees ----------------
__global__ void __launch_bounds__(1024) k_scan(int n) {
    __shared__ int buf[1024];
    __shared__ int carry;
    if (threadIdx.x == 0) carry = 0;
    __syncthreads();
    for (int base = 0; base < n; base += 1024) {
        const int i = base + threadIdx.x;
        const int v = (i < n) ? g_deg[i] : 0;
        buf[threadIdx.x] = v;
        __syncthreads();
#pragma unroll
        for (int d = 1; d < 1024; d <<= 1) {
            int t = (threadIdx.x >= d) ? buf[threadIdx.x - d] : 0;
            __syncthreads();
            buf[threadIdx.x] += t;
            __syncthreads();
        }
        if (i < n) {
            const int excl = carry + buf[threadIdx.x] - v;
            g_off[i] = excl;
            g_cur[i] = excl;
        }
        __syncthreads();
        if (threadIdx.x == 1023) carry += buf[1023];
        __syncthreads();
    }
    if (threadIdx.x == 0) g_off[n] = carry;
}

// ---------------- CSR fill ----------------
__global__ void k_fill(const int* __restrict__ row, const int* __restrict__ col, int E) {
    int e = blockIdx.x * blockDim.x + threadIdx.x;
    if (e < E) {
        const int pos = atomicAdd(&g_cur[col[e]], 1);
        g_adj[pos] = row[e];
    }
}

// ---------------- tiled fp32 GEMM: C[M,N] = A[M,K] @ B[K,N], rows scaled by dinv ----------------
template<int N, int K>
__global__ void __launch_bounds__(256) k_gemm(const float* __restrict__ A,
                                              const float* __restrict__ B,
                                              float* __restrict__ C, int M) {
    constexpr int BM = 128, BN = 64, BK = 16;
    __shared__ float As[BK][BM + 1];
    __shared__ float Bs[BK][BN];

    const int tid = threadIdx.x;
    const int bm = blockIdx.x * BM;
    const int bn = blockIdx.y * BN;
    const int tx = tid & 15;
    const int ty = tid >> 4;
    const int tm0 = ty * 8;
    const int tn0 = tx * 4;

    const int ar = tid >> 2;        // 0..63
    const int ac = (tid & 3) * 4;   // 0,4,8,12
    const int br = tid >> 4;        // 0..15
    const int bc = (tid & 15) * 4;  // 0..60

    float acc[8][4];
#pragma unroll
    for (int i = 0; i < 8; i++)
#pragma unroll
        for (int j = 0; j < 4; j++) acc[i][j] = 0.f;

    for (int k0 = 0; k0 < K; k0 += BK) {
#pragma unroll
        for (int h = 0; h < 2; h++) {
            const int r = ar + h * 64;
            const int grow = bm + r;
            float4 v = make_float4(0.f, 0.f, 0.f, 0.f);
            if (grow < M)
                v = *reinterpret_cast<const float4*>(A + (size_t)grow * K + k0 + ac);
            As[ac + 0][r] = v.x; As[ac + 1][r] = v.y;
            As[ac + 2][r] = v.z; As[ac + 3][r] = v.w;
        }
        {
            const float4 bv = *reinterpret_cast<const float4*>(B + (size_t)(k0 + br) * N + bn + bc);
            *reinterpret_cast<float4*>(&Bs[br][bc]) = bv;
        }
        __syncthreads();

#pragma unroll
        for (int k = 0; k < BK; k++) {
            float ra[8], rb[4];
#pragma unroll
            for (int i = 0; i < 8; i++) ra[i] = As[k][tm0 + i];
#pragma unroll
            for (int j = 0; j < 4; j++) rb[j] = Bs[k][tn0 + j];
#pragma unroll
            for (int i = 0; i < 8; i++)
#pragma unroll
                for (int j = 0; j < 4; j++) acc[i][j] = fmaf(ra[i], rb[j], acc[i][j]);
        }
        __syncthreads();
    }

#pragma unroll
    for (int i = 0; i < 8; i++) {
        const int grow = bm + tm0 + i;
        if (grow < M) {
            const float s = g_dinv[grow];
            float4 v = make_float4(acc[i][0] * s, acc[i][1] * s, acc[i][2] * s, acc[i][3] * s);
            *reinterpret_cast<float4*>(C + (size_t)grow * N + bn + tn0) = v;
        }
    }
}

// ---------------- CSR gather: out[c] = b + dinv[c]*(hs[c] + sum_{r in adj(c)} hs[r]) ----------------
template<int F, bool RELU>
__global__ void __launch_bounds__(256) k_gather(const float* __restrict__ hs,
                                                const float* __restrict__ bias,
                                                float* __restrict__ out, int n) {
    constexpr int TPN = F / 4;          // threads per node (1 float4 each)
    constexpr int NPB = 256 / TPN;      // nodes per block
    const int node = blockIdx.x * NPB + threadIdx.x / TPN;
    const int lane = threadIdx.x % TPN;
    if (node >= n) return;
    const int f4 = lane * 4;

    float4 acc = *reinterpret_cast<const float4*>(hs + (size_t)node * F + f4);  // self-loop term
    const int s = g_off[node];
    const int t = g_off[node + 1];
    for (int i = s; i < t; i++) {
        const int r = g_adj[i];
        const float4 v = __ldg(reinterpret_cast<const float4*>(hs + (size_t)r * F + f4));
        acc.x += v.x; acc.y += v.y; acc.z += v.z; acc.w += v.w;
    }
    const float di = g_dinv[node];
    const float4 b = *reinterpret_cast<const float4*>(bias + f4);
    float4 o;
    o.x = fmaf(acc.x, di, b.x);
    o.y = fmaf(acc.y, di, b.y);
    o.z = fmaf(acc.z, di, b.z);
    o.w = fmaf(acc.w, di, b.w);
    if (RELU) {
        o.x = fmaxf(o.x, 0.f); o.y = fmaxf(o.y, 0.f);
        o.z = fmaxf(o.z, 0.f); o.w = fmaxf(o.w, 0.f);
    }
    *reinterpret_cast<float4*>(out + (size_t)node * F + f4) = o;
}

extern "C" void kernel_launch(void* const* d_in, const int* in_sizes, int n_in,
                              void* d_out, int out_size) {
    const float* x   = (const float*)d_in[0];
    const int*   ei  = (const int*)d_in[1];     // int32 (JAX x64 disabled)
    const float* W1  = (const float*)d_in[2];
    const float* b1  = (const float*)d_in[3];
    const float* W2  = (const float*)d_in[4];
    const float* b2  = (const float*)d_in[5];
    float*       out = (float*)d_out;

    const int M = in_sizes[0] / FIN;        // 50000 nodes
    const int E = in_sizes[1] / 2;          // 800000 edges
    const int* row = ei;
    const int* col = ei + E;

    const int T = 256;

    // degree + dinv + CSR build
    k_zero_deg<<<(M + T - 1) / T, T>>>(M);
    k_count<<<(E + T - 1) / T, T>>>(col, E);
    k_dinv<<<(M + T - 1) / T, T>>>(M);
    k_scan<<<1, 1024>>>(M);
    k_fill<<<(E + T - 1) / T, T>>>(row, col, E);

    // layer 1: h1 = (x @ W1) * dinv[row]
    {
        dim3 grid((M + 127) / 128, FH / 64);
        k_gemm<FH, FIN><<<grid, T>>>(x, W1, g_h1, M);
    }
    // a1 = relu(b1 + dinv[c]*(h1[c] + sum h1[r]))
    {
        const int NPB = 256 / (FH / 4);
        k_gather<FH, true><<<(M + NPB - 1) / NPB, T>>>(g_h1, b1, g_a1, M);
    }

    // layer 2: h2 = (a1 @ W2) * dinv[row]
    {
        dim3 grid((M + 127) / 128, FO / 64);
        k_gemm<FO, FH><<<grid, T>>>(g_a1, W2, g_h2, M);
    }
    // out = b2 + dinv[c]*(h2[c] + sum h2[r])
    {
        const int NPB = 256 / (FO / 4);
        k_gather<FO, false><<<(M + NPB - 1) / NPB, T>>>(g_h2, b2, out, M);
    }
}

// round 5
// speedup vs baseline: 5.4677x; 1.0458x over previous
#include <cuda_runtime.h>
#include <stdint.h>

#define MAX_NODES 50000
#define MAX_EDGES 1000000
#define FIN 512
#define FH  256
#define FO  64

// ---- scratch (no allocations allowed) ----
__device__ int   g_deg[MAX_NODES];
__device__ int   g_bsum[256];
__device__ int   g_off[MAX_NODES + 1];
__device__ int   g_cur[MAX_NODES];
__device__ int   g_adj[MAX_EDGES];               // source node per CSR slot
__device__ float g_wgt[MAX_EDGES];               // dinv[row]*dinv[col] per CSR slot
__device__ float g_dinv[MAX_NODES];
__device__ float g_h1[(size_t)MAX_NODES * FH];   // x @ W1 (raw)
__device__ float g_a1[(size_t)MAX_NODES * FH];   // relu(aggregated layer-1)
__device__ float g_h2[(size_t)MAX_NODES * FO];   // a1 @ W2 (raw)

__global__ void k_noop() {}

__global__ void k_zero_deg(int n) {
    int i = blockIdx.x * blockDim.x + threadIdx.x;
    if (i < n) g_deg[i] = 0;
}

__global__ void k_count(const int* __restrict__ col, int E) {
    int i = blockIdx.x * blockDim.x + threadIdx.x;
    if (i < E) atomicAdd(&g_deg[col[i]], 1);
}

// ---------------- scan stage 1: per-block degree sums ----------------
__global__ void __launch_bounds__(256) k_scan_part(int n) {
    __shared__ int sh[256];
    const int tid = threadIdx.x;
    const int i = blockIdx.x * 256 + tid;
    sh[tid] = (i < n) ? g_deg[i] : 0;
    __syncthreads();
#pragma unroll
    for (int d = 128; d > 0; d >>= 1) {
        if (tid < d) sh[tid] += sh[tid + d];
        __syncthreads();
    }
    if (tid == 0) g_bsum[blockIdx.x] = sh[0];
}

// ---------------- scan stage 2: block base + local exclusive scan + dinv ----------------
__global__ void __launch_bounds__(256) k_scan_final(int n, int E) {
    __shared__ int sh[256];
    const int tid = threadIdx.x;
    const int i = blockIdx.x * 256 + tid;

    sh[tid] = (tid < blockIdx.x) ? g_bsum[tid] : 0;
    __syncthreads();
#pragma unroll
    for (int d = 128; d > 0; d >>= 1) {
        if (tid < d) sh[tid] += sh[tid + d];
        __syncthreads();
    }
    const int base = sh[0];
    __syncthreads();

    const int v = (i < n) ? g_deg[i] : 0;
    sh[tid] = v;
    __syncthreads();
#pragma unroll
    for (int d = 1; d < 256; d <<= 1) {
        const int t = (tid >= d) ? sh[tid - d] : 0;
        __syncthreads();
        sh[tid] += t;
        __syncthreads();
    }
    if (i < n) {
        const int excl = base + sh[tid] - v;
        g_off[i] = excl;
        g_cur[i] = excl;
        g_dinv[i] = rsqrtf((float)(v + 1));  // +1 self-loop
        if (i == n - 1) g_off[n] = E;
    }
}

// ---------------- CSR fill (+ per-slot weight) ----------------
__global__ void k_fill(const int* __restrict__ row, const int* __restrict__ col, int E) {
    int e = blockIdx.x * blockDim.x + threadIdx.x;
    if (e < E) {
        const int r = row[e];
        const int c = col[e];
        const int pos = atomicAdd(&g_cur[c], 1);
        g_adj[pos] = r;
        g_wgt[pos] = g_dinv[r] * g_dinv[c];
    }
}

// ---------------- tiled fp32 GEMM: C[M,N] = A[M,K] @ B[K,N] ----------------
template<int N, int K>
__global__ void __launch_bounds__(256) k_gemm(const float* __restrict__ A,
                                              const float* __restrict__ B,
                                              float* __restrict__ C, int M) {
    constexpr int BM = 128, BN = 64, BK = 16;
    __shared__ float As[BK][BM + 1];
    __shared__ float Bs[BK][BN];

    const int tid = threadIdx.x;
    const int bm = blockIdx.x * BM;
    const int bn = blockIdx.y * BN;
    const int tx = tid & 15;
    const int ty = tid >> 4;
    const int tm0 = ty * 8;
    const int tn0 = tx * 4;

    const int ar = tid >> 2;
    const int ac = (tid & 3) * 4;
    const int br = tid >> 4;
    const int bc = (tid & 15) * 4;

    float acc[8][4];
#pragma unroll
    for (int i = 0; i < 8; i++)
#pragma unroll
        for (int j = 0; j < 4; j++) acc[i][j] = 0.f;

    for (int k0 = 0; k0 < K; k0 += BK) {
#pragma unroll
        for (int h = 0; h < 2; h++) {
            const int r = ar + h * 64;
            const int grow = bm + r;
            float4 v = make_float4(0.f, 0.f, 0.f, 0.f);
            if (grow < M)
                v = *reinterpret_cast<const float4*>(A + (size_t)grow * K + k0 + ac);
            As[ac + 0][r] = v.x; As[ac + 1][r] = v.y;
            As[ac + 2][r] = v.z; As[ac + 3][r] = v.w;
        }
        {
            const float4 bv = *reinterpret_cast<const float4*>(B + (size_t)(k0 + br) * N + bn + bc);
            *reinterpret_cast<float4*>(&Bs[br][bc]) = bv;
        }
        __syncthreads();

#pragma unroll
        for (int k = 0; k < BK; k++) {
            float ra[8], rb[4];
#pragma unroll
            for (int i = 0; i < 8; i++) ra[i] = As[k][tm0 + i];
#pragma unroll
            for (int j = 0; j < 4; j++) rb[j] = Bs[k][tn0 + j];
#pragma unroll
            for (int i = 0; i < 8; i++)
#pragma unroll
                for (int j = 0; j < 4; j++) acc[i][j] = fmaf(ra[i], rb[j], acc[i][j]);
        }
        __syncthreads();
    }

#pragma unroll
    for (int i = 0; i < 8; i++) {
        const int grow = bm + tm0 + i;
        if (grow < M) {
            float4 v = make_float4(acc[i][0], acc[i][1], acc[i][2], acc[i][3]);
            *reinterpret_cast<float4*>(C + (size_t)grow * N + bn + tn0) = v;
        }
    }
}

// ---------------- CSR gather, warp per (node, chunk) ----------------
// out[c] = b + dinv[c]^2*h[c] + sum_i w_i * h[adj_i]
template<int F, int VEC, bool RELU>
__global__ void __launch_bounds__(256) k_gather(const float* __restrict__ hs,
                                                const float* __restrict__ bias,
                                                float* __restrict__ out, int n) {
    constexpr int CHUNK = 32 * VEC;
    constexpr int CPN = F / CHUNK;
    const int wid = blockIdx.x * 8 + (threadIdx.x >> 5);
    const int node = wid / CPN;
    if (node >= n) return;
    const int chunk = wid % CPN;
    const int lane = threadIdx.x & 31;
    const int f0 = chunk * CHUNK + lane * VEC;

    const float di = g_dinv[node];
    const float di2 = di * di;

    float acc[VEC];
    if constexpr (VEC == 4) {
        const float4 v = *reinterpret_cast<const float4*>(hs + (size_t)node * F + f0);
        acc[0] = v.x * di2; acc[1] = v.y * di2; acc[2] = v.z * di2; acc[3] = v.w * di2;
    } else {
        const float2 v = *reinterpret_cast<const float2*>(hs + (size_t)node * F + f0);
        acc[0] = v.x * di2; acc[1] = v.y * di2;
    }

    const int s = g_off[node];
    const int t = g_off[node + 1];
    for (int base = s; base < t; base += 32) {
        const int idx = base + lane;
        int   a = 0;
        float w = 0.f;
        if (idx < t) { a = g_adj[idx]; w = g_wgt[idx]; }
        const int m = min(32, t - base);
        int j = 0;
        for (; j + 4 <= m; j += 4) {
            const int r0 = __shfl_sync(0xffffffffu, a, j);
            const int r1 = __shfl_sync(0xffffffffu, a, j + 1);
            const int r2 = __shfl_sync(0xffffffffu, a, j + 2);
            const int r3 = __shfl_sync(0xffffffffu, a, j + 3);
            const float w0 = __shfl_sync(0xffffffffu, w, j);
            const float w1 = __shfl_sync(0xffffffffu, w, j + 1);
            const float w2 = __shfl_sync(0xffffffffu, w, j + 2);
            const float w3 = __shfl_sync(0xffffffffu, w, j + 3);
            if constexpr (VEC == 4) {
                const float4 v0 = __ldg(reinterpret_cast<const float4*>(hs + (size_t)r0 * F + f0));
                const float4 v1 = __ldg(reinterpret_cast<const float4*>(hs + (size_t)r1 * F + f0));
                const float4 v2 = __ldg(reinterpret_cast<const float4*>(hs + (size_t)r2 * F + f0));
                const float4 v3 = __ldg(reinterpret_cast<const float4*>(hs + (size_t)r3 * F + f0));
                acc[0] += fmaf(w0, v0.x, fmaf(w1, v1.x, fmaf(w2, v2.x, w3 * v3.x)));
                acc[1] += fmaf(w0, v0.y, fmaf(w1, v1.y, fmaf(w2, v2.y, w3 * v3.y)));
                acc[2] += fmaf(w0, v0.z, fmaf(w1, v1.z, fmaf(w2, v2.z, w3 * v3.z)));
                acc[3] += fmaf(w0, v0.w, fmaf(w1, v1.w, fmaf(w2, v2.w, w3 * v3.w)));
            } else {
                const float2 v0 = __ldg(reinterpret_cast<const float2*>(hs + (size_t)r0 * F + f0));
                const float2 v1 = __ldg(reinterpret_cast<const float2*>(hs + (size_t)r1 * F + f0));
                const float2 v2 = __ldg(reinterpret_cast<const float2*>(hs + (size_t)r2 * F + f0));
                const float2 v3 = __ldg(reinterpret_cast<const float2*>(hs + (size_t)r3 * F + f0));
                acc[0] += fmaf(w0, v0.x, fmaf(w1, v1.x, fmaf(w2, v2.x, w3 * v3.x)));
                acc[1] += fmaf(w0, v0.y, fmaf(w1, v1.y, fmaf(w2, v2.y, w3 * v3.y)));
            }
        }
        for (; j < m; j++) {
            const int rr = __shfl_sync(0xffffffffu, a, j);
            const float ww = __shfl_sync(0xffffffffu, w, j);
            if constexpr (VEC == 4) {
                const float4 v = __ldg(reinterpret_cast<const float4*>(hs + (size_t)rr * F + f0));
                acc[0] = fmaf(ww, v.x, acc[0]); acc[1] = fmaf(ww, v.y, acc[1]);
                acc[2] = fmaf(ww, v.z, acc[2]); acc[3] = fmaf(ww, v.w, acc[3]);
            } else {
                const float2 v = __ldg(reinterpret_cast<const float2*>(hs + (size_t)rr * F + f0));
                acc[0] = fmaf(ww, v.x, acc[0]); acc[1] = fmaf(ww, v.y, acc[1]);
            }
        }
    }

    if constexpr (VEC == 4) {
        const float4 b = *reinterpret_cast<const float4*>(bias + f0);
        float4 o = make_float4(acc[0] + b.x, acc[1] + b.y, acc[2] + b.z, acc[3] + b.w);
        if (RELU) {
            o.x = fmaxf(o.x, 0.f); o.y = fmaxf(o.y, 0.f);
            o.z = fmaxf(o.z, 0.f); o.w = fmaxf(o.w, 0.f);
        }
        *reinterpret_cast<float4*>(out + (size_t)node * F + f0) = o;
    } else {
        const float2 b = *reinterpret_cast<const float2*>(bias + f0);
        float2 o = make_float2(acc[0] + b.x, acc[1] + b.y);
        if (RELU) { o.x = fmaxf(o.x, 0.f); o.y = fmaxf(o.y, 0.f); }
        *reinterpret_cast<float2*>(out + (size_t)node * F + f0) = o;
    }
}

extern "C" void kernel_launch(void* const* d_in, const int* in_sizes, int n_in,
                              void* d_out, int out_size) {
    const float* x   = (const float*)d_in[0];
    const int*   ei  = (const int*)d_in[1];
    const float* W1  = (const float*)d_in[2];
    const float* b1  = (const float*)d_in[3];
    const float* W2  = (const float*)d_in[4];
    const float* b2  = (const float*)d_in[5];
    float*       out = (float*)d_out;

    const int M = in_sizes[0] / FIN;        // 50000
    const int E = in_sizes[1] / 2;          // 800000
    const int* row = ei;
    const int* col = ei + E;

    const int T = 256;
    const int nblk = (M + 255) / 256;       // 196 <= 256

    k_zero_deg<<<nblk, T>>>(M);                                   // 0
    {                                                             // 1: gemm1 (graph-independent now)
        dim3 grid((M + 127) / 128, FH / 64);
        k_gemm<FH, FIN><<<grid, T>>>(x, W1, g_h1, M);
    }
    k_noop<<<1, 32>>>();                                          // 2
    k_count<<<(E + T - 1) / T, T>>>(col, E);                      // 3  <- profiled slot
    k_scan_part<<<nblk, T>>>(M);                                  // 4
    k_scan_final<<<nblk, T>>>(M, E);                              // 5
    k_fill<<<(E + T - 1) / T, T>>>(row, col, E);                  // 6

    {                                                             // 7: gather1 (relu)
        const int warps = M * (FH / 128);
        k_gather<FH, 4, true><<<(warps + 7) / 8, T>>>(g_h1, b1, g_a1, M);
    }
    {                                                             // 8: gemm2
        dim3 grid((M + 127) / 128, FO / 64);
        k_gemm<FO, FH><<<grid, T>>>(g_a1, W2, g_h2, M);
    }
    {                                                             // 9: gather2
        const int warps = M;
        k_gather<FO, 2, false><<<(warps + 7) / 8, T>>>(g_h2, b2, out, M);
    }
}

// round 6
// speedup vs baseline: 5.8506x; 1.0700x over previous
#include <cuda_runtime.h>
#include <stdint.h>

#define MAX_NODES 50000
#define MAX_EDGES 1000000
#define FIN 512
#define FH  256
#define FO  64

// ---- scratch (no allocations allowed) ----
__device__ int   g_deg[MAX_NODES];
__device__ int   g_off[MAX_NODES + 1];
__device__ int   g_cur[MAX_NODES];
__device__ int   g_adj[MAX_EDGES];               // source node per CSR slot
__device__ float g_wgt[MAX_EDGES];               // dinv[row]*dinv[col] per CSR slot
__device__ float g_dinv[MAX_NODES];
__device__ float g_h1[(size_t)MAX_NODES * FH];   // x @ W1 (raw)
__device__ float g_a1[(size_t)MAX_NODES * FH];   // relu(aggregated layer-1)
__device__ float g_h2[(size_t)MAX_NODES * FO];   // a1 @ W2 (raw)

__global__ void k_zero_deg(int n) {
    int i = blockIdx.x * blockDim.x + threadIdx.x;
    if (i < n) g_deg[i] = 0;
}

__global__ void k_count(const int* __restrict__ col, int E) {
    int i = blockIdx.x * blockDim.x + threadIdx.x;
    if (i < E) atomicAdd(&g_deg[col[i]], 1);
}

// ---------------- single-block scan: offsets + cursors + dinv ----------------
__global__ void __launch_bounds__(1024) k_scan(int n, int E) {
    const int CH = (n + 1023) >> 10;            // elems per thread (49 for n=50000)
    const int tid = threadIdx.x;
    const int lane = tid & 31;
    const int wrp = tid >> 5;
    const int start = tid * CH;

    int sum = 0;
    for (int j = 0; j < CH; j++) {
        const int i = start + j;
        if (i < n) sum += g_deg[i];
    }

    // block-wide exclusive scan of per-thread sums
    __shared__ int wsum[32];
    int v = sum;
#pragma unroll
    for (int d = 1; d < 32; d <<= 1) {
        const int t = __shfl_up_sync(0xffffffffu, v, d);
        if (lane >= d) v += t;
    }
    if (lane == 31) wsum[wrp] = v;
    __syncthreads();
    if (wrp == 0) {
        int w = wsum[lane];
#pragma unroll
        for (int d = 1; d < 32; d <<= 1) {
            const int t = __shfl_up_sync(0xffffffffu, w, d);
            if (lane >= d) w += t;
        }
        wsum[lane] = w;
    }
    __syncthreads();

    int run = (v - sum) + (wrp > 0 ? wsum[wrp - 1] : 0);
    for (int j = 0; j < CH; j++) {
        const int i = start + j;
        if (i < n) {
            const int d = g_deg[i];
            g_off[i] = run;
            g_cur[i] = run;
            g_dinv[i] = rsqrtf((float)(d + 1));  // +1 self-loop
            run += d;
        }
    }
    if (tid == 1023) g_off[n] = E;
}

// ---------------- CSR fill (+ per-slot weight) ----------------
__global__ void k_fill(const int* __restrict__ row, const int* __restrict__ col, int E) {
    int e = blockIdx.x * blockDim.x + threadIdx.x;
    if (e < E) {
        const int r = row[e];
        const int c = col[e];
        const int pos = atomicAdd(&g_cur[c], 1);
        g_adj[pos] = r;
        g_wgt[pos] = g_dinv[r] * g_dinv[c];
    }
}

// ---------------- tiled fp32 GEMM: C[M,N] = A[M,K] @ B[K,N] ----------------
template<int N, int K>
__global__ void __launch_bounds__(256) k_gemm(const float* __restrict__ A,
                                              const float* __restrict__ B,
                                              float* __restrict__ C, int M) {
    constexpr int BM = 128, BN = 64, BK = 16;
    __shared__ float As[BK][BM + 1];
    __shared__ float Bs[BK][BN];

    const int tid = threadIdx.x;
    const int bm = blockIdx.x * BM;
    const int bn = blockIdx.y * BN;
    const int tx = tid & 15;
    const int ty = tid >> 4;
    const int tm0 = ty * 8;
    const int tn0 = tx * 4;

    const int ar = tid >> 2;
    const int ac = (tid & 3) * 4;
    const int br = tid >> 4;
    const int bc = (tid & 15) * 4;

    float acc[8][4];
#pragma unroll
    for (int i = 0; i < 8; i++)
#pragma unroll
        for (int j = 0; j < 4; j++) acc[i][j] = 0.f;

    for (int k0 = 0; k0 < K; k0 += BK) {
#pragma unroll
        for (int h = 0; h < 2; h++) {
            const int r = ar + h * 64;
            const int grow = bm + r;
            float4 v = make_float4(0.f, 0.f, 0.f, 0.f);
            if (grow < M)
                v = *reinterpret_cast<const float4*>(A + (size_t)grow * K + k0 + ac);
            As[ac + 0][r] = v.x; As[ac + 1][r] = v.y;
            As[ac + 2][r] = v.z; As[ac + 3][r] = v.w;
        }
        {
            const float4 bv = *reinterpret_cast<const float4*>(B + (size_t)(k0 + br) * N + bn + bc);
            *reinterpret_cast<float4*>(&Bs[br][bc]) = bv;
        }
        __syncthreads();

#pragma unroll
        for (int k = 0; k < BK; k++) {
            float ra[8], rb[4];
#pragma unroll
            for (int i = 0; i < 8; i++) ra[i] = As[k][tm0 + i];
#pragma unroll
            for (int j = 0; j < 4; j++) rb[j] = Bs[k][tn0 + j];
#pragma unroll
            for (int i = 0; i < 8; i++)
#pragma unroll
                for (int j = 0; j < 4; j++) acc[i][j] = fmaf(ra[i], rb[j], acc[i][j]);
        }
        __syncthreads();
    }

#pragma unroll
    for (int i = 0; i < 8; i++) {
        const int grow = bm + tm0 + i;
        if (grow < M) {
            float4 v = make_float4(acc[i][0], acc[i][1], acc[i][2], acc[i][3]);
            *reinterpret_cast<float4*>(C + (size_t)grow * N + bn + tn0) = v;
        }
    }
}

// ---------------- CSR gather, warp per (node, chunk) ----------------
// out[c] = b + dinv[c]^2*h[c] + sum_i w_i * h[adj_i]
template<int F, int VEC, bool RELU>
__global__ void __launch_bounds__(256) k_gather(const float* __restrict__ hs,
                                                const float* __restrict__ bias,
                                                float* __restrict__ out, int n) {
    constexpr int CHUNK = 32 * VEC;
    constexpr int CPN = F / CHUNK;
    const int wid = blockIdx.x * 8 + (threadIdx.x >> 5);
    const int node = wid / CPN;
    if (node >= n) return;
    const int chunk = wid % CPN;
    const int lane = threadIdx.x & 31;
    const int f0 = chunk * CHUNK + lane * VEC;

    const float di = g_dinv[node];
    const float di2 = di * di;

    float acc[VEC];
    if constexpr (VEC == 4) {
        const float4 v = *reinterpret_cast<const float4*>(hs + (size_t)node * F + f0);
        acc[0] = v.x * di2; acc[1] = v.y * di2; acc[2] = v.z * di2; acc[3] = v.w * di2;
    } else {
        const float2 v = *reinterpret_cast<const float2*>(hs + (size_t)node * F + f0);
        acc[0] = v.x * di2; acc[1] = v.y * di2;
    }

    const int s = g_off[node];
    const int t = g_off[node + 1];
    for (int base = s; base < t; base += 32) {
        const int idx = base + lane;
        int   a = 0;
        float w = 0.f;
        if (idx < t) { a = g_adj[idx]; w = g_wgt[idx]; }
        const int m = min(32, t - base);
        int j = 0;
        for (; j + 4 <= m; j += 4) {
            const int r0 = __shfl_sync(0xffffffffu, a, j);
            const int r1 = __shfl_sync(0xffffffffu, a, j + 1);
            const int r2 = __shfl_sync(0xffffffffu, a, j + 2);
            const int r3 = __shfl_sync(0xffffffffu, a, j + 3);
            const float w0 = __shfl_sync(0xffffffffu, w, j);
            const float w1 = __shfl_sync(0xffffffffu, w, j + 1);
            const float w2 = __shfl_sync(0xffffffffu, w, j + 2);
            const float w3 = __shfl_sync(0xffffffffu, w, j + 3);
            if constexpr (VEC == 4) {
                const float4 v0 = __ldg(reinterpret_cast<const float4*>(hs + (size_t)r0 * F + f0));
                const float4 v1 = __ldg(reinterpret_cast<const float4*>(hs + (size_t)r1 * F + f0));
                const float4 v2 = __ldg(reinterpret_cast<const float4*>(hs + (size_t)r2 * F + f0));
                const float4 v3 = __ldg(reinterpret_cast<const float4*>(hs + (size_t)r3 * F + f0));
                acc[0] += fmaf(w0, v0.x, fmaf(w1, v1.x, fmaf(w2, v2.x, w3 * v3.x)));
                acc[1] += fmaf(w0, v0.y, fmaf(w1, v1.y, fmaf(w2, v2.y, w3 * v3.y)));
                acc[2] += fmaf(w0, v0.z, fmaf(w1, v1.z, fmaf(w2, v2.z, w3 * v3.z)));
                acc[3] += fmaf(w0, v0.w, fmaf(w1, v1.w, fmaf(w2, v2.w, w3 * v3.w)));
            } else {
                const float2 v0 = __ldg(reinterpret_cast<const float2*>(hs + (size_t)r0 * F + f0));
                const float2 v1 = __ldg(reinterpret_cast<const float2*>(hs + (size_t)r1 * F + f0));
                const float2 v2 = __ldg(reinterpret_cast<const float2*>(hs + (size_t)r2 * F + f0));
                const float2 v3 = __ldg(reinterpret_cast<const float2*>(hs + (size_t)r3 * F + f0));
                acc[0] += fmaf(w0, v0.x, fmaf(w1, v1.x, fmaf(w2, v2.x, w3 * v3.x)));
                acc[1] += fmaf(w0, v0.y, fmaf(w1, v1.y, fmaf(w2, v2.y, w3 * v3.y)));
            }
        }
        for (; j < m; j++) {
            const int rr = __shfl_sync(0xffffffffu, a, j);
            const float ww = __shfl_sync(0xffffffffu, w, j);
            if constexpr (VEC == 4) {
                const float4 v = __ldg(reinterpret_cast<const float4*>(hs + (size_t)rr * F + f0));
                acc[0] = fmaf(ww, v.x, acc[0]); acc[1] = fmaf(ww, v.y, acc[1]);
                acc[2] = fmaf(ww, v.z, acc[2]); acc[3] = fmaf(ww, v.w, acc[3]);
            } else {
                const float2 v = __ldg(reinterpret_cast<const float2*>(hs + (size_t)rr * F + f0));
                acc[0] = fmaf(ww, v.x, acc[0]); acc[1] = fmaf(ww, v.y, acc[1]);
            }
        }
    }

    if constexpr (VEC == 4) {
        const float4 b = *reinterpret_cast<const float4*>(bias + f0);
        float4 o = make_float4(acc[0] + b.x, acc[1] + b.y, acc[2] + b.z, acc[3] + b.w);
        if (RELU) {
            o.x = fmaxf(o.x, 0.f); o.y = fmaxf(o.y, 0.f);
            o.z = fmaxf(o.z, 0.f); o.w = fmaxf(o.w, 0.f);
        }
        *reinterpret_cast<float4*>(out + (size_t)node * F + f0) = o;
    } else {
        const float2 b = *reinterpret_cast<const float2*>(bias + f0);
        float2 o = make_float2(acc[0] + b.x, acc[1] + b.y);
        if (RELU) { o.x = fmaxf(o.x, 0.f); o.y = fmaxf(o.y, 0.f); }
        *reinterpret_cast<float2*>(out + (size_t)node * F + f0) = o;
    }
}

extern "C" void kernel_launch(void* const* d_in, const int* in_sizes, int n_in,
                              void* d_out, int out_size) {
    const float* x   = (const float*)d_in[0];
    const int*   ei  = (const int*)d_in[1];
    const float* W1  = (const float*)d_in[2];
    const float* b1  = (const float*)d_in[3];
    const float* W2  = (const float*)d_in[4];
    const float* b2  = (const float*)d_in[5];
    float*       out = (float*)d_out;

    const int M = in_sizes[0] / FIN;        // 50000
    const int E = in_sizes[1] / 2;          // 800000
    const int* row = ei;
    const int* col = ei + E;

    const int T = 256;
    const int nblk = (M + 255) / 256;

    k_zero_deg<<<nblk, T>>>(M);                                   // 0
    k_count<<<(E + T - 1) / T, T>>>(col, E);                      // 1
    k_scan<<<1, 1024>>>(M, E);                                    // 2
    k_fill<<<(E + T - 1) / T, T>>>(row, col, E);                  // 3  <- profiled slot
    {                                                             // 4: gemm1
        dim3 grid((M + 127) / 128, FH / 64);
        k_gemm<FH, FIN><<<grid, T>>>(x, W1, g_h1, M);
    }
    {                                                             // 5: gather1 (relu)
        const int warps = M * (FH / 128);
        k_gather<FH, 4, true><<<(warps + 7) / 8, T>>>(g_h1, b1, g_a1, M);
    }
    {                                                             // 6: gemm2
        dim3 grid((M + 127) / 128, FO / 64);
        k_gemm<FO, FH><<<grid, T>>>(g_a1, W2, g_h2, M);
    }
    {                                                             // 7: gather2
        const int warps = M;
        k_gather<FO, 2, false><<<(warps + 7) / 8, T>>>(g_h2, b2, out, M);
    }
}